// round 9
// baseline (speedup 1.0000x reference)
#include <cuda_runtime.h>
#include <stdint.h>
#include <float.h>

#define Bq 8
#define Nq 6
#define Mq 64
#define Vq 32000
#define Tq 8
#define NS 7                   // Nq+1 template slots
#define MV (Mq * Vq)
#define MV2 (MV / 2)           // float2 stride between n-planes
#define V2 (Vq / 2)            // 16000 float2 per row
#define V4 (Vq / 4)
#define CHK 4                  // v-chunks per (b,m) row
#define C2 (V2 / CHK)          // 4000 float2 per chunk
#define NIT 16                 // ceil(C2 / TPB) stage slots (last partially full)
#define TPB 256
#define NSTG 3                 // cp.async pipeline stages
#define TASKS_PER_B (Mq * CHK) // 256

// scratch (no allocs allowed)
__device__ float g_pmax[Bq * Mq * CHK][Tq];  // per-task partial max per t
__device__ float g_out0[Bq * Mq][Tq];        // out[b,t,m,v=0] (pad included at m==0)
__device__ int   g_cnt[Bq];                  // completion tickets (zero-init; scanner resets)

union PU { unsigned long long u; float2 f; };
union XU { float4 f4; float f[4]; };

__device__ __forceinline__ unsigned long long fma2(unsigned long long a,
                                                   unsigned long long b,
                                                   unsigned long long c)
{
    unsigned long long d;
    asm("fma.rn.f32x2 %0, %1, %2, %3;" : "=l"(d) : "l"(a), "l"(b), "l"(c));
    return d;
}

__device__ __forceinline__ void cp_async8(const void* smem_ptr, const void* gaddr)
{
    unsigned int saddr = (unsigned int)__cvta_generic_to_shared(smem_ptr);
    asm volatile("cp.async.ca.shared.global [%0], [%1], 8;" :: "r"(saddr), "l"(gaddr));
}
#define CP_COMMIT()  asm volatile("cp.async.commit_group;")
#define CP_WAIT(n)   asm volatile("cp.async.wait_group %0;" :: "n"(n))

// ---------------------------------------------------------------------------
// Single fused kernel: one block per (b,m,chunk).
//  - streams its chunk of X[b,:,m,:] via 3-stage cp.async pipeline
//  - writes speculative t=0 row; publishes partial maxes
//  - the LAST finisher per batch scans + fixes mispredicted rows inline
// ---------------------------------------------------------------------------
__global__ __launch_bounds__(TPB, 2)
void k_all(const float* __restrict__ X,
           const float* __restrict__ tmplt,
           const int*   __restrict__ spans,
           float*       __restrict__ out)
{
    const int task = blockIdx.x;
    const int b = task >> 8;          // TASKS_PER_B = 256 tasks per batch
    const int m = (task >> 2) & 63;
    const int c = task & 3;
    const int tid = threadIdx.x;

    __shared__ float2 stage[NSTG][Nq][TPB];   // 36.9 KB
    __shared__ float  sw[Tq][NS];
    __shared__ float  s_red[8][Tq];
    __shared__ int    s_ticket;
    __shared__ int    s_bits[Mq];
    __shared__ unsigned long long s_mask[Tq];
    __shared__ int    s_rowmap[Mq];

    if (tid < Tq * NS) {
        const float val = tmplt[b * Tq * NS + tid];
        sw[tid / NS][tid % NS] = ((tid % NS) <= spans[b]) ? val : 0.0f;
    }
    __syncthreads();

    // weights packed over t-pairs: w2[tp][n] = (w[2tp][n], w[2tp+1][n])
    PU w2[4][Nq];
#pragma unroll
    for (int tp = 0; tp < 4; tp++)
#pragma unroll
        for (int n = 0; n < Nq; n++) {
            w2[tp][n].f.x = sw[2 * tp][n + 1];
            w2[tp][n].f.y = sw[2 * tp + 1][n + 1];
        }

    const size_t base = (size_t)b * Nq * MV + (size_t)m * Vq;   // float units
    const float2* X2  = reinterpret_cast<const float2*>(X) + (base >> 1);
    float2*       o2  = reinterpret_cast<float2*>(out + (size_t)(b * Mq + m) * Vq);

    // pre-step: out0[t] (chunk 0 only)
    if (c == 0 && tid == 0) {
        float xv[Nq];
#pragma unroll
        for (int n = 0; n < Nq; n++) xv[n] = X[base + (size_t)n * MV];
#pragma unroll
        for (int t = 0; t < Tq; t++) {
            float o = 0.0f;
#pragma unroll
            for (int n = 0; n < Nq; n++) o = fmaf(sw[t][n + 1], xv[n], o);
            if (m == 0) o += sw[t][0];
            g_out0[b * Mq + m][t] = o;
        }
    }

    float tmax[Tq];
#pragma unroll
    for (int t = 0; t < Tq; t++) tmax[t] = -FLT_MAX;

    const int i0   = c * C2;
    const int iend = (c + 1) * C2;

#define ISSUE(s, k)                                                            \
    do { const int _i = i0 + (k) * TPB + tid;                                  \
         if (_i < iend) {                                                      \
             _Pragma("unroll")                                                 \
             for (int n = 0; n < Nq; n++)                                      \
                 cp_async8(&stage[s][n][tid], X2 + n * MV2 + _i);              \
         }                                                                     \
         CP_COMMIT();                                                          \
    } while (0)

#define COMPUTE(s, k)                                                          \
    do { CP_WAIT(NSTG - 1);                                                    \
         const int _i = i0 + (k) * TPB + tid;                                  \
         if (_i < iend) {                                                      \
             float2 xb[Nq];                                                    \
             _Pragma("unroll")                                                 \
             for (int n = 0; n < Nq; n++) xb[n] = stage[s][n][tid];            \
             float ox, oy;                                                     \
             _Pragma("unroll")                                                 \
             for (int j = 0; j < 2; j++) {                                     \
                 PU acc[4];                                                    \
                 _Pragma("unroll")                                             \
                 for (int tp = 0; tp < 4; tp++) acc[tp].u = 0ull;              \
                 _Pragma("unroll")                                             \
                 for (int n = 0; n < Nq; n++) {                                \
                     PU xx; const float sgl = j ? xb[n].y : xb[n].x;           \
                     xx.f.x = sgl; xx.f.y = sgl;                               \
                     _Pragma("unroll")                                         \
                     for (int tp = 0; tp < 4; tp++)                            \
                         acc[tp].u = fma2(xx.u, w2[tp][n].u, acc[tp].u);       \
                 }                                                             \
                 _Pragma("unroll")                                             \
                 for (int tp = 0; tp < 4; tp++) {                              \
                     tmax[2 * tp]     = fmaxf(tmax[2 * tp],     acc[tp].f.x);  \
                     tmax[2 * tp + 1] = fmaxf(tmax[2 * tp + 1], acc[tp].f.y);  \
                 }                                                             \
                 if (j == 0) ox = acc[0].f.x; else oy = acc[0].f.x;            \
             }                                                                 \
             float2 o; o.x = ox; o.y = oy;                                     \
             __stcs(o2 + _i, o);                                               \
         }                                                                     \
    } while (0)

    ISSUE(0, 0);
    ISSUE(1, 1);
    ISSUE(2, 2);

#pragma unroll 1
    for (int k = 0; k < NIT; k += NSTG) {
        COMPUTE(0, k);     ISSUE(0, k + 3);
        COMPUTE(1, k + 1); ISSUE(1, k + 4);
        COMPUTE(2, k + 2); ISSUE(2, k + 5);
    }
    CP_WAIT(0);
#undef ISSUE
#undef COMPUTE

    // pad one-hot on the speculative row: tid0 of (c==0,m==0) wrote v=0 itself
    if (c == 0 && m == 0 && tid == 0) {
        float2 v = __ldcg(o2);
        v.x += sw[0][0];
        __stcg(o2, v);
    }

    // block-reduce 8 maxes -> g_pmax[task]
    const int lane = tid & 31, wq = tid >> 5;
#pragma unroll
    for (int t = 0; t < Tq; t++) {
        float v = tmax[t];
#pragma unroll
        for (int off = 16; off; off >>= 1)
            v = fmaxf(v, __shfl_xor_sync(0xffffffffu, v, off));
        if (lane == 0) s_red[wq][t] = v;
    }
    __syncthreads();
    if (tid < Tq) {
        float mx = s_red[0][tid];
#pragma unroll
        for (int q = 1; q < 8; q++) mx = fmaxf(mx, s_red[q][tid]);
        g_pmax[task][tid] = mx;
    }

    // ---- publish (release) + ticket ----
    __threadfence();
    __syncthreads();
    if (tid == 0) s_ticket = atomicAdd(&g_cnt[b], 1);
    __syncthreads();
    if (s_ticket != TASKS_PER_B - 1) return;

    // ======== last finisher for batch b: scan + fix ========
    __threadfence();   // acquire

    if (tid < Mq) s_bits[tid] = 0;
    __syncthreads();

    for (int mt = tid; mt < Mq * Tq; mt += TPB) {      // 2 per thread
        const int mm = mt >> 3, t = mt & 7;
        float mx = -FLT_MAX;
#pragma unroll
        for (int cc = 0; cc < CHK; cc++)
            mx = fmaxf(mx, g_pmax[(b * Mq + mm) * CHK + cc][t]);
        // argmax_v==0  <=>  out0(padded) >= raw max (pad weight >= 0; ties -> 0)
        if (g_out0[b * Mq + mm][t] >= mx) atomicOr(&s_bits[mm], 1 << t);
    }
    __syncthreads();

    if (tid < Tq) {
        unsigned long long mk = 0ull;
        for (int mm = 0; mm < Mq; mm++)
            if ((s_bits[mm] >> tid) & 1) mk |= (1ull << mm);
        s_mask[tid] = mk;
    }
    __syncthreads();

    if (tid == 0) {
        int idx = 0;
        for (int t = 0; t < Tq; t++) {
            const unsigned long long mk = s_mask[t];
            const int first = mk ? (__ffsll((long long)mk) - 1) : Mq;
            const int len = min(first, Mq - idx);
            for (int q = idx; q < idx + len; q++)
                s_rowmap[q] = (t << 8) | (q - idx);
            idx += len;
        }
        for (int q = idx; q < Mq; q++) s_rowmap[q] = -1;
        g_cnt[b] = 0;                       // reset for next graph replay
    }
    __syncthreads();

    // fix mispredicted rows (normally none on this data; correct on any data)
    for (int p = 0; p < Mq; p++) {
        const int rm = s_rowmap[p];
        if (rm == p) continue;              // speculation (t=0, mloc=p) exact

        float* row = out + (size_t)(b * Mq + p) * Vq;

        if (rm < 0) {                       // never written in reference -> zeros
            const float4 z = make_float4(0.f, 0.f, 0.f, 0.f);
            for (int i4 = tid; i4 < V4; i4 += TPB)
                reinterpret_cast<float4*>(row)[i4] = z;
            continue;
        }

        const int t = rm >> 8, mloc = rm & 255;
        const size_t fb = (size_t)b * Nq * MV + (size_t)mloc * Vq;
        for (int i4 = tid; i4 < V4; i4 += TPB) {
            const int v = i4 * 4;
            XU x[Nq]; XU o;
#pragma unroll
            for (int n = 0; n < Nq; n++)
                x[n].f4 = *reinterpret_cast<const float4*>(X + fb + (size_t)n * MV + v);
#pragma unroll
            for (int j = 0; j < 4; j++) {
                float acc = 0.0f;
#pragma unroll
                for (int n = 0; n < Nq; n++) acc = fmaf(sw[t][n + 1], x[n].f[j], acc);
                o.f[j] = acc;
            }
            if (i4 == 0 && mloc == 0) o.f[0] += sw[t][0];
            *reinterpret_cast<float4*>(row + v) = o.f4;
        }
    }
}

extern "C" void kernel_launch(void* const* d_in, const int* in_sizes, int n_in,
                              void* d_out, int out_size)
{
    const float* X     = (const float*)d_in[0];
    const float* tmplt = (const float*)d_in[1];
    const int*   spans = (const int*)d_in[2];
    float*       out   = (float*)d_out;

    k_all<<<Bq * Mq * CHK, TPB>>>(X, tmplt, spans, out);
}

// round 10
// speedup vs baseline: 1.0105x; 1.0105x over previous
#include <cuda_runtime.h>
#include <stdint.h>
#include <float.h>

#define Bq 8
#define Nq 6
#define Mq 64
#define Vq 32000
#define Tq 8
#define NS 7                   // Nq+1 template slots
#define MV (Mq * Vq)
#define MV2 (MV / 2)           // float2 stride between n-planes
#define V2 (Vq / 2)            // 16000 float2 per row
#define V4 (Vq / 4)
#define CHK 4                  // v-chunks per (b,m) row
#define C2 (V2 / CHK)          // 4000 float2 per chunk
#define NIT 16                 // stage slots
#define TPB 256
#define NSTG 3                 // cp.async pipeline stages
#define TASKS_PER_B (Mq * CHK) // 256

// scratch (no allocs allowed)
// g_pmax laid out [b][m][t][chunk] so the scanner gathers with LDG.128
__device__ float g_pmax[Bq * Mq * Tq * CHK];
__device__ float g_out0[Bq * Mq][Tq];   // out[b,t,m,v=0] (pad included at m==0)
__device__ int   g_cnt[Bq];             // tickets (zero-init; scanner resets)

union PU { unsigned long long u; float2 f; };
union XU { float4 f4; float f[4]; };

__device__ __forceinline__ unsigned long long fma2(unsigned long long a,
                                                   unsigned long long b,
                                                   unsigned long long c)
{
    unsigned long long d;
    asm("fma.rn.f32x2 %0, %1, %2, %3;" : "=l"(d) : "l"(a), "l"(b), "l"(c));
    return d;
}

__device__ __forceinline__ void cp_async8(const void* smem_ptr, const void* gaddr)
{
    unsigned int saddr = (unsigned int)__cvta_generic_to_shared(smem_ptr);
    asm volatile("cp.async.ca.shared.global [%0], [%1], 8;" :: "r"(saddr), "l"(gaddr));
}
#define CP_COMMIT()  asm volatile("cp.async.commit_group;")
#define CP_WAIT(n)   asm volatile("cp.async.wait_group %0;" :: "n"(n))

// acq_rel gpu-scope ticket: release (orders this block's prior stores, after
// __syncthreads made them program-order-prior for tid0) + acquire (orders the
// scanner's subsequent loads). NO fence instruction -> no CCTL.IVALL flush.
__device__ __forceinline__ int ticket_acq_rel(int* addr)
{
    int old;
    asm volatile("atom.acq_rel.gpu.global.add.s32 %0, [%1], 1;"
                 : "=r"(old) : "l"(addr) : "memory");
    return old;
}

// ---------------------------------------------------------------------------
// Single fused kernel: one block per (b,m,chunk).
//  - streams its chunk of X[b,:,m,:] via 3-stage cp.async pipeline (R8-proven)
//  - writes speculative t=0 row; publishes partial maxes
//  - LAST ticket per batch: scan + fix mispredicted rows inline
// ---------------------------------------------------------------------------
__global__ __launch_bounds__(TPB, 2)
void k_all(const float* __restrict__ X,
           const float* __restrict__ tmplt,
           const int*   __restrict__ spans,
           float*       __restrict__ out)
{
    const int task = blockIdx.x;
    const int b = task >> 8;          // 256 tasks per batch
    const int m = (task >> 2) & 63;
    const int c = task & 3;
    const int tid = threadIdx.x;

    __shared__ float2 stage[NSTG][Nq][TPB];   // 36.9 KB
    __shared__ float  sw[Tq][NS];
    __shared__ float  s_red[8][Tq];
    __shared__ int    s_ticket;
    __shared__ int    s_bits[Mq];
    __shared__ unsigned long long s_mask[Tq];
    __shared__ int    s_rowmap[Mq];

    if (tid < Tq * NS) {
        const float val = tmplt[b * Tq * NS + tid];
        sw[tid / NS][tid % NS] = ((tid % NS) <= spans[b]) ? val : 0.0f;
    }
    __syncthreads();

    PU w2[4][Nq];
#pragma unroll
    for (int tp = 0; tp < 4; tp++)
#pragma unroll
        for (int n = 0; n < Nq; n++) {
            w2[tp][n].f.x = sw[2 * tp][n + 1];
            w2[tp][n].f.y = sw[2 * tp + 1][n + 1];
        }

    const size_t base = (size_t)b * Nq * MV + (size_t)m * Vq;
    const float2* X2  = reinterpret_cast<const float2*>(X) + (base >> 1);
    float2*       o2  = reinterpret_cast<float2*>(out + (size_t)(b * Mq + m) * Vq);

    // pre-step: out0[t] (chunk 0 only)
    if (c == 0 && tid == 0) {
        float xv[Nq];
#pragma unroll
        for (int n = 0; n < Nq; n++) xv[n] = X[base + (size_t)n * MV];
#pragma unroll
        for (int t = 0; t < Tq; t++) {
            float o = 0.0f;
#pragma unroll
            for (int n = 0; n < Nq; n++) o = fmaf(sw[t][n + 1], xv[n], o);
            if (m == 0) o += sw[t][0];
            g_out0[b * Mq + m][t] = o;
        }
    }

    float tmax[Tq];
#pragma unroll
    for (int t = 0; t < Tq; t++) tmax[t] = -FLT_MAX;

    const int i0   = c * C2;
    const int iend = (c + 1) * C2;

#define ISSUE(s, k)                                                            \
    do { const int _i = i0 + (k) * TPB + tid;                                  \
         if (_i < iend) {                                                      \
             _Pragma("unroll")                                                 \
             for (int n = 0; n < Nq; n++)                                      \
                 cp_async8(&stage[s][n][tid], X2 + n * MV2 + _i);              \
         }                                                                     \
         CP_COMMIT();                                                          \
    } while (0)

#define COMPUTE(s, k)                                                          \
    do { CP_WAIT(NSTG - 1);                                                    \
         const int _i = i0 + (k) * TPB + tid;                                  \
         if (_i < iend) {                                                      \
             float2 xb[Nq];                                                    \
             _Pragma("unroll")                                                 \
             for (int n = 0; n < Nq; n++) xb[n] = stage[s][n][tid];            \
             float ox, oy;                                                     \
             _Pragma("unroll")                                                 \
             for (int j = 0; j < 2; j++) {                                     \
                 PU acc[4];                                                    \
                 _Pragma("unroll")                                             \
                 for (int tp = 0; tp < 4; tp++) acc[tp].u = 0ull;              \
                 _Pragma("unroll")                                             \
                 for (int n = 0; n < Nq; n++) {                                \
                     PU xx; const float sgl = j ? xb[n].y : xb[n].x;           \
                     xx.f.x = sgl; xx.f.y = sgl;                               \
                     _Pragma("unroll")                                         \
                     for (int tp = 0; tp < 4; tp++)                            \
                         acc[tp].u = fma2(xx.u, w2[tp][n].u, acc[tp].u);       \
                 }                                                             \
                 _Pragma("unroll")                                             \
                 for (int tp = 0; tp < 4; tp++) {                              \
                     tmax[2 * tp]     = fmaxf(tmax[2 * tp],     acc[tp].f.x);  \
                     tmax[2 * tp + 1] = fmaxf(tmax[2 * tp + 1], acc[tp].f.y);  \
                 }                                                             \
                 if (j == 0) ox = acc[0].f.x; else oy = acc[0].f.x;            \
             }                                                                 \
             float2 o; o.x = ox; o.y = oy;                                     \
             __stcs(o2 + _i, o);                                               \
         }                                                                     \
    } while (0)

    ISSUE(0, 0);
    ISSUE(1, 1);
    ISSUE(2, 2);

#pragma unroll 1
    for (int k = 0; k < NIT; k += NSTG) {
        COMPUTE(0, k);     ISSUE(0, k + 3);
        COMPUTE(1, k + 1); ISSUE(1, k + 4);
        COMPUTE(2, k + 2); ISSUE(2, k + 5);
    }
    CP_WAIT(0);
#undef ISSUE
#undef COMPUTE

    if (c == 0 && m == 0 && tid == 0) {
        float2 v = __ldcg(o2);
        v.x += sw[0][0];
        __stcg(o2, v);
    }

    // block-reduce 8 maxes -> g_pmax[b][m][t][c]
    const int lane = tid & 31, wq = tid >> 5;
#pragma unroll
    for (int t = 0; t < Tq; t++) {
        float v = tmax[t];
#pragma unroll
        for (int off = 16; off; off >>= 1)
            v = fmaxf(v, __shfl_xor_sync(0xffffffffu, v, off));
        if (lane == 0) s_red[wq][t] = v;
    }
    __syncthreads();
    if (tid < Tq) {
        float mx = s_red[0][tid];
#pragma unroll
        for (int q = 1; q < 8; q++) mx = fmaxf(mx, s_red[q][tid]);
        g_pmax[((b * Mq + m) * Tq + tid) * CHK + c] = mx;
    }

    // ---- ticket: syncthreads (CTA ordering) + acq_rel atomic (gpu scope) ----
    __syncthreads();
    if (tid == 0) s_ticket = ticket_acq_rel(&g_cnt[b]);
    __syncthreads();
    if (s_ticket != TASKS_PER_B - 1) return;

    // ======== last finisher for batch b: scan + fix ========
    if (tid < Mq) s_bits[tid] = 0;
    if (tid == 0) g_cnt[b] = 0;             // reset for next graph replay
    __syncthreads();

    for (int mt = tid; mt < Mq * Tq; mt += TPB) {      // 2 per thread
        const int mm = mt >> 3, t = mt & 7;
        // one 16B L2-direct load gets all 4 chunk partials
        const float4 p4 = __ldcg(reinterpret_cast<const float4*>(
            &g_pmax[((b * Mq + mm) * Tq + t) * CHK]));
        const float mx = fmaxf(fmaxf(p4.x, p4.y), fmaxf(p4.z, p4.w));
        // argmax_v==0  <=>  out0(padded) >= raw max (pad weight >= 0; ties -> 0)
        if (__ldcg(&g_out0[b * Mq + mm][t]) >= mx) atomicOr(&s_bits[mm], 1 << t);
    }
    __syncthreads();

    if (tid < Tq) {
        unsigned long long mk = 0ull;
        for (int mm = 0; mm < Mq; mm++)
            if ((s_bits[mm] >> tid) & 1) mk |= (1ull << mm);
        s_mask[tid] = mk;
    }
    __syncthreads();

    if (tid == 0) {
        int idx = 0;
        for (int t = 0; t < Tq; t++) {
            const unsigned long long mk = s_mask[t];
            const int first = mk ? (__ffsll((long long)mk) - 1) : Mq;
            const int len = min(first, Mq - idx);
            for (int q = idx; q < idx + len; q++)
                s_rowmap[q] = (t << 8) | (q - idx);
            idx += len;
        }
        for (int q = idx; q < Mq; q++) s_rowmap[q] = -1;
    }
    __syncthreads();

    // fix mispredicted rows (normally none on this data; correct on any data)
    for (int p = 0; p < Mq; p++) {
        const int rm = s_rowmap[p];
        if (rm == p) continue;              // speculation (t=0, mloc=p) exact

        float* row = out + (size_t)(b * Mq + p) * Vq;

        if (rm < 0) {                       // never written in reference -> zeros
            const float4 z = make_float4(0.f, 0.f, 0.f, 0.f);
            for (int i4 = tid; i4 < V4; i4 += TPB)
                reinterpret_cast<float4*>(row)[i4] = z;
            continue;
        }

        const int t = rm >> 8, mloc = rm & 255;
        const size_t fb = (size_t)b * Nq * MV + (size_t)mloc * Vq;
        for (int i4 = tid; i4 < V4; i4 += TPB) {
            const int v = i4 * 4;
            XU x[Nq]; XU o;
#pragma unroll
            for (int n = 0; n < Nq; n++)
                x[n].f4 = *reinterpret_cast<const float4*>(X + fb + (size_t)n * MV + v);
#pragma unroll
            for (int j = 0; j < 4; j++) {
                float acc = 0.0f;
#pragma unroll
                for (int n = 0; n < Nq; n++) acc = fmaf(sw[t][n + 1], x[n].f[j], acc);
                o.f[j] = acc;
            }
            if (i4 == 0 && mloc == 0) o.f[0] += sw[t][0];
            *reinterpret_cast<float4*>(row + v) = o.f4;
        }
    }
}

extern "C" void kernel_launch(void* const* d_in, const int* in_sizes, int n_in,
                              void* d_out, int out_size)
{
    const float* X     = (const float*)d_in[0];
    const float* tmplt = (const float*)d_in[1];
    const int*   spans = (const int*)d_in[2];
    float*       out   = (float*)d_out;

    k_all<<<Bq * Mq * CHK, TPB>>>(X, tmplt, spans, out);
}

// round 12
// speedup vs baseline: 2.2780x; 2.2543x over previous
#include <cuda_runtime.h>
#include <stdint.h>
#include <float.h>

#define Bq 8
#define Nq 6
#define Mq 64
#define Vq 32000
#define Tq 8
#define NS 7                   // Nq+1 template slots
#define MV (Mq * Vq)
#define MV2 (MV / 2)           // float2 stride between n-planes
#define V2 (Vq / 2)            // 16000 float2 per row
#define V4 (Vq / 4)
#define CHK 4                  // v-chunks per (b,m) row
#define C2 (V2 / CHK)          // 4000 float2 per chunk
#define NIT 16                 // stage slots
#define TPB 256
#define NSTG 3                 // cp.async pipeline stages

// scratch (no allocs allowed)
// g_pmax laid out [b][m][t][chunk] so k_fix gathers with LDG.128
__device__ float g_pmax[Bq * Mq * Tq * CHK];
__device__ float g_out0[Bq * Mq][Tq];   // out[b,t,m,v=0] (pad included at m==0)

union PU { unsigned long long u; float2 f; };
union XU { float4 f4; float f[4]; };

__device__ __forceinline__ unsigned long long fma2(unsigned long long a,
                                                   unsigned long long b,
                                                   unsigned long long c)
{
    unsigned long long d;
    asm("fma.rn.f32x2 %0, %1, %2, %3;" : "=l"(d) : "l"(a), "l"(b), "l"(c));
    return d;
}

__device__ __forceinline__ void cp_async8(const void* smem_ptr, const void* gaddr)
{
    unsigned int saddr = (unsigned int)__cvta_generic_to_shared(smem_ptr);
    asm volatile("cp.async.ca.shared.global [%0], [%1], 8;" :: "r"(saddr), "l"(gaddr));
}
#define CP_COMMIT()  asm volatile("cp.async.commit_group;")
#define CP_WAIT(n)   asm volatile("cp.async.wait_group %0;" :: "n"(n))

// ---------------------------------------------------------------------------
// K1: one block per (b,m,chunk). 3-stage cp.async pipeline; dup-free packed
// f32x2 mainloop: 8 packed accumulators over (even,odd) v-elements, weights
// pre-duplicated -> 48 FFMA2 + 16 FMNMX per float2, no broadcast MOVs.
// ---------------------------------------------------------------------------
__global__ __launch_bounds__(TPB, 2)
void k_pass1(const float* __restrict__ X,
             const float* __restrict__ tmplt,
             const int*   __restrict__ spans,
             float*       __restrict__ out)
{
    const int task = blockIdx.x;
    const int b = task >> 8;          // 256 tasks per batch
    const int m = (task >> 2) & 63;
    const int c = task & 3;
    const int tid = threadIdx.x;

    __shared__ float2 stage[NSTG][Nq][TPB];   // 36.9 KB
    __shared__ float  sw[Tq][NS];
    __shared__ float  s_red[8][Tq];

    if (tid < Tq * NS) {
        const float val = tmplt[b * Tq * NS + tid];
        sw[tid / NS][tid % NS] = ((tid % NS) <= spans[b]) ? val : 0.0f;
    }
    __syncthreads();

    // weights duplicated into packed pairs: w2[t][n] = (w[t][n], w[t][n])
    PU w2[Tq][Nq];
#pragma unroll
    for (int t = 0; t < Tq; t++)
#pragma unroll
        for (int n = 0; n < Nq; n++) {
            w2[t][n].f.x = sw[t][n + 1];
            w2[t][n].f.y = sw[t][n + 1];
        }

    const size_t base = (size_t)b * Nq * MV + (size_t)m * Vq;
    const float2* X2  = reinterpret_cast<const float2*>(X) + (base >> 1);
    float2*       o2  = reinterpret_cast<float2*>(out + (size_t)(b * Mq + m) * Vq);

    // pre-step: out0[t] (chunk 0 only)
    if (c == 0 && tid == 0) {
        float xv[Nq];
#pragma unroll
        for (int n = 0; n < Nq; n++) xv[n] = X[base + (size_t)n * MV];
#pragma unroll
        for (int t = 0; t < Tq; t++) {
            float o = 0.0f;
#pragma unroll
            for (int n = 0; n < Nq; n++) o = fmaf(sw[t][n + 1], xv[n], o);
            if (m == 0) o += sw[t][0];
            g_out0[b * Mq + m][t] = o;
        }
    }

    float tmax[Tq];
#pragma unroll
    for (int t = 0; t < Tq; t++) tmax[t] = -FLT_MAX;

    const int i0   = c * C2;
    const int iend = (c + 1) * C2;

#define ISSUE(s, k)                                                            \
    do { const int _i = i0 + (k) * TPB + tid;                                  \
         if (_i < iend) {                                                      \
             _Pragma("unroll")                                                 \
             for (int n = 0; n < Nq; n++)                                      \
                 cp_async8(&stage[s][n][tid], X2 + n * MV2 + _i);              \
         }                                                                     \
         CP_COMMIT();                                                          \
    } while (0)

#define COMPUTE(s, k)                                                          \
    do { CP_WAIT(NSTG - 1);                                                    \
         const int _i = i0 + (k) * TPB + tid;                                  \
         if (_i < iend) {                                                      \
             PU xb[Nq];                                                        \
             _Pragma("unroll")                                                 \
             for (int n = 0; n < Nq; n++) xb[n].f = stage[s][n][tid];          \
             PU acc[Tq];                                                       \
             _Pragma("unroll")                                                 \
             for (int t = 0; t < Tq; t++) acc[t].u = 0ull;                     \
             _Pragma("unroll")                                                 \
             for (int n = 0; n < Nq; n++) {                                    \
                 _Pragma("unroll")                                             \
                 for (int t = 0; t < Tq; t++)                                  \
                     acc[t].u = fma2(xb[n].u, w2[t][n].u, acc[t].u);           \
             }                                                                 \
             _Pragma("unroll")                                                 \
             for (int t = 0; t < Tq; t++)                                      \
                 tmax[t] = fmaxf(tmax[t], fmaxf(acc[t].f.x, acc[t].f.y));      \
             __stcs(o2 + _i, acc[0].f);   /* speculative t=0 row */            \
         }                                                                     \
    } while (0)

    ISSUE(0, 0);
    ISSUE(1, 1);
    ISSUE(2, 2);

#pragma unroll 1
    for (int k = 0; k < NIT; k += NSTG) {
        COMPUTE(0, k);     ISSUE(0, k + 3);
        COMPUTE(1, k + 1); ISSUE(1, k + 4);
        COMPUTE(2, k + 2); ISSUE(2, k + 5);
    }
    CP_WAIT(0);
#undef ISSUE
#undef COMPUTE

    // pad one-hot on the speculative row: tid0 of (c==0,m==0) wrote v=0 itself
    if (c == 0 && m == 0 && tid == 0) {
        float2 v = __ldcg(o2);
        v.x += sw[0][0];
        __stcg(o2, v);
    }

    // block-reduce 8 maxes -> g_pmax[b][m][t][c]
    const int lane = tid & 31, wq = tid >> 5;
#pragma unroll
    for (int t = 0; t < Tq; t++) {
        float v = tmax[t];
#pragma unroll
        for (int off = 16; off; off >>= 1)
            v = fmaxf(v, __shfl_xor_sync(0xffffffffu, v, off));
        if (lane == 0) s_red[wq][t] = v;
    }
    __syncthreads();
    if (tid < Tq) {
        float mx = s_red[0][tid];
#pragma unroll
        for (int q = 1; q < 8; q++) mx = fmaxf(mx, s_red[q][tid]);
        g_pmax[((b * Mq + m) * Tq + tid) * CHK + c] = mx;
    }
}

// ---------------------------------------------------------------------------
// K2: one block per (b,p). Atomics-free scan rebuild (thread mm owns its
// row's mask), then fixes this row only if the t=0 speculation was wrong.
// ---------------------------------------------------------------------------
__global__ __launch_bounds__(TPB) void k_fix(const float* __restrict__ X,
                                             const float* __restrict__ tmplt,
                                             const int*   __restrict__ spans,
                                             float*       __restrict__ out)
{
    const int bx  = blockIdx.x;
    const int b   = bx >> 6;
    const int p   = bx & 63;
    const int tid = threadIdx.x;

    __shared__ int                s_bits[Mq];
    __shared__ unsigned long long s_mask[Tq];
    __shared__ int                s_rowmap[Mq];

    if (tid < Mq) {
        const int mm = tid;
        int mask = 0;
#pragma unroll
        for (int t = 0; t < Tq; t++) {
            const float4 p4 = *reinterpret_cast<const float4*>(
                &g_pmax[((b * Mq + mm) * Tq + t) * CHK]);
            const float mx = fmaxf(fmaxf(p4.x, p4.y), fmaxf(p4.z, p4.w));
            // argmax_v==0 <=> out0(padded) >= raw max (pad weight >= 0; ties -> 0)
            if (g_out0[b * Mq + mm][t] >= mx) mask |= (1 << t);
        }
        s_bits[mm] = mask;
    }
    __syncthreads();

    if (tid < Tq) {
        unsigned long long mk = 0ull;
        for (int mm = 0; mm < Mq; mm++)
            if ((s_bits[mm] >> tid) & 1) mk |= (1ull << mm);
        s_mask[tid] = mk;
    }
    __syncthreads();

    if (tid == 0) {
        int idx = 0;
        for (int t = 0; t < Tq; t++) {
            const unsigned long long mk = s_mask[t];
            const int first = mk ? (__ffsll((long long)mk) - 1) : Mq;
            const int len = min(first, Mq - idx);
            for (int q = idx; q < idx + len; q++)
                s_rowmap[q] = (t << 8) | (q - idx);
            idx += len;
        }
        for (int q = idx; q < Mq; q++) s_rowmap[q] = -1;
    }
    __syncthreads();

    const int rm = s_rowmap[p];
    if (rm == p) return;                    // speculation (t=0, mloc=p) exact

    float* row = out + (size_t)(b * Mq + p) * Vq;

    if (rm < 0) {                           // never written in reference -> zeros
        const float4 z = make_float4(0.f, 0.f, 0.f, 0.f);
        for (int i4 = tid; i4 < V4; i4 += TPB)
            reinterpret_cast<float4*>(row)[i4] = z;
        return;
    }

    const int t = rm >> 8, mloc = rm & 255;
    float wv[NS];
#pragma unroll
    for (int s = 0; s < NS; s++) {
        const float val = tmplt[b * Tq * NS + t * NS + s];
        wv[s] = (s <= spans[b]) ? val : 0.0f;
    }
    const size_t fb = (size_t)b * Nq * MV + (size_t)mloc * Vq;
    for (int i4 = tid; i4 < V4; i4 += TPB) {
        const int v = i4 * 4;
        XU x[Nq]; XU o;
#pragma unroll
        for (int n = 0; n < Nq; n++)
            x[n].f4 = *reinterpret_cast<const float4*>(X + fb + (size_t)n * MV + v);
#pragma unroll
        for (int j = 0; j < 4; j++) {
            float acc = 0.0f;
#pragma unroll
            for (int n = 0; n < Nq; n++) acc = fmaf(wv[n + 1], x[n].f[j], acc);
            o.f[j] = acc;
        }
        if (i4 == 0 && mloc == 0) o.f[0] += wv[0];
        *reinterpret_cast<float4*>(row + v) = o.f4;
    }
}

extern "C" void kernel_launch(void* const* d_in, const int* in_sizes, int n_in,
                              void* d_out, int out_size)
{
    const float* X     = (const float*)d_in[0];
    const float* tmplt = (const float*)d_in[1];
    const int*   spans = (const int*)d_in[2];
    float*       out   = (float*)d_out;

    k_pass1<<<Bq * Mq * CHK, TPB>>>(X, tmplt, spans, out);
    k_fix<<<Bq * Mq, TPB>>>(X, tmplt, spans, out);
}

// round 13
// speedup vs baseline: 2.3794x; 1.0445x over previous
#include <cuda_runtime.h>
#include <stdint.h>
#include <float.h>

#define Bq 8
#define Nq 6
#define Mq 64
#define Vq 32000
#define Tq 8
#define NS 7                   // Nq+1 template slots
#define MV (Mq * Vq)
#define MV4 (MV / 4)           // float4 stride between n-planes
#define V4 (Vq / 4)            // 8000 float4 per row
#define CHK 4                  // v-chunks per (b,m) row
#define C4 (V4 / CHK)          // 2000 float4 per chunk
#define NIT4 8                 // ceil(C4 / TPB) slots (last partial)
#define TPB 256
#define NSTG 3                 // cp.async pipeline stages
#define SMEM_DYN (NSTG * Nq * TPB * 16)   // 73728 B stage buffer

// scratch (no allocs allowed)
// g_pmax laid out [b][m][t][chunk] so k_fix gathers with LDG.128
__device__ float g_pmax[Bq * Mq * Tq * CHK];
__device__ float g_out0[Bq * Mq][Tq];   // out[b,t,m,v=0] (pad included at m==0)

union PU { unsigned long long u; float2 f; };
union XU { float4 f4; float f[4]; };

__device__ __forceinline__ unsigned long long fma2(unsigned long long a,
                                                   unsigned long long b,
                                                   unsigned long long c)
{
    unsigned long long d;
    asm("fma.rn.f32x2 %0, %1, %2, %3;" : "=l"(d) : "l"(a), "l"(b), "l"(c));
    return d;
}

__device__ __forceinline__ void cp_async16(const void* smem_ptr, const void* gaddr)
{
    unsigned int saddr = (unsigned int)__cvta_generic_to_shared(smem_ptr);
    asm volatile("cp.async.cg.shared.global [%0], [%1], 16;" :: "r"(saddr), "l"(gaddr));
}
#define CP_COMMIT()  asm volatile("cp.async.commit_group;")
#define CP_WAIT(n)   asm volatile("cp.async.wait_group %0;" :: "n"(n))

// ---------------------------------------------------------------------------
// K1: one block per (b,m,chunk). 3-stage cp.async.cg 16B pipeline; float4
// compute with packed f32x2 accumulators (lo pair then hi pair, regs reused).
// Halves LSU ops per byte vs the 8B version.
// ---------------------------------------------------------------------------
__global__ __launch_bounds__(TPB, 2)
void k_pass1(const float* __restrict__ X,
             const float* __restrict__ tmplt,
             const int*   __restrict__ spans,
             float*       __restrict__ out)
{
    extern __shared__ float4 stage[];   // [NSTG][Nq][TPB]
    __shared__ float sw[Tq][NS];
    __shared__ float s_red[8][Tq];

    const int task = blockIdx.x;
    const int b = task >> 8;          // 256 tasks per batch
    const int m = (task >> 2) & 63;
    const int c = task & 3;
    const int tid = threadIdx.x;

    if (tid < Tq * NS) {
        const float val = tmplt[b * Tq * NS + tid];
        sw[tid / NS][tid % NS] = ((tid % NS) <= spans[b]) ? val : 0.0f;
    }
    __syncthreads();

    // weights duplicated into packed pairs: w2[t][n] = (w[t][n], w[t][n])
    PU w2[Tq][Nq];
#pragma unroll
    for (int t = 0; t < Tq; t++)
#pragma unroll
        for (int n = 0; n < Nq; n++) {
            w2[t][n].f.x = sw[t][n + 1];
            w2[t][n].f.y = sw[t][n + 1];
        }

    const size_t base = (size_t)b * Nq * MV + (size_t)m * Vq;
    const float4* X4  = reinterpret_cast<const float4*>(X) + (base >> 2);
    float4*       o4  = reinterpret_cast<float4*>(out + (size_t)(b * Mq + m) * Vq);

    // pre-step: out0[t] (chunk 0 only)
    if (c == 0 && tid == 0) {
        float xv[Nq];
#pragma unroll
        for (int n = 0; n < Nq; n++) xv[n] = X[base + (size_t)n * MV];
#pragma unroll
        for (int t = 0; t < Tq; t++) {
            float o = 0.0f;
#pragma unroll
            for (int n = 0; n < Nq; n++) o = fmaf(sw[t][n + 1], xv[n], o);
            if (m == 0) o += sw[t][0];
            g_out0[b * Mq + m][t] = o;
        }
    }

    float tmax[Tq];
#pragma unroll
    for (int t = 0; t < Tq; t++) tmax[t] = -FLT_MAX;

    const int i0   = c * C4;
    const int iend = (c + 1) * C4;

#define STG_SLOT(s, n) stage[((s) * Nq + (n)) * TPB + tid]

#define ISSUE(s, k)                                                            \
    do { const int _i = i0 + (k) * TPB + tid;                                  \
         if (_i < iend) {                                                      \
             _Pragma("unroll")                                                 \
             for (int n = 0; n < Nq; n++)                                      \
                 cp_async16(&STG_SLOT(s, n), X4 + n * MV4 + _i);               \
         }                                                                     \
         CP_COMMIT();                                                          \
    } while (0)

#define COMPUTE(s, k)                                                          \
    do { CP_WAIT(NSTG - 1);                                                    \
         const int _i = i0 + (k) * TPB + tid;                                  \
         if (_i < iend) {                                                      \
             XU xb[Nq];                                                        \
             _Pragma("unroll")                                                 \
             for (int n = 0; n < Nq; n++) xb[n].f4 = STG_SLOT(s, n);           \
             PU acc[Tq];                                                       \
             float2 keep;                                                      \
             /* lo pair (elements 0,1) */                                      \
             _Pragma("unroll")                                                 \
             for (int t = 0; t < Tq; t++) acc[t].u = 0ull;                     \
             _Pragma("unroll")                                                 \
             for (int n = 0; n < Nq; n++) {                                    \
                 PU xp; xp.f.x = xb[n].f[0]; xp.f.y = xb[n].f[1];              \
                 _Pragma("unroll")                                             \
                 for (int t = 0; t < Tq; t++)                                  \
                     acc[t].u = fma2(xp.u, w2[t][n].u, acc[t].u);              \
             }                                                                 \
             _Pragma("unroll")                                                 \
             for (int t = 0; t < Tq; t++)                                      \
                 tmax[t] = fmaxf(tmax[t], fmaxf(acc[t].f.x, acc[t].f.y));      \
             keep = acc[0].f;                                                  \
             /* hi pair (elements 2,3), accumulators reused */                 \
             _Pragma("unroll")                                                 \
             for (int t = 0; t < Tq; t++) acc[t].u = 0ull;                     \
             _Pragma("unroll")                                                 \
             for (int n = 0; n < Nq; n++) {                                    \
                 PU xp; xp.f.x = xb[n].f[2]; xp.f.y = xb[n].f[3];              \
                 _Pragma("unroll")                                             \
                 for (int t = 0; t < Tq; t++)                                  \
                     acc[t].u = fma2(xp.u, w2[t][n].u, acc[t].u);              \
             }                                                                 \
             _Pragma("unroll")                                                 \
             for (int t = 0; t < Tq; t++)                                      \
                 tmax[t] = fmaxf(tmax[t], fmaxf(acc[t].f.x, acc[t].f.y));      \
             float4 o;                                                         \
             o.x = keep.x; o.y = keep.y; o.z = acc[0].f.x; o.w = acc[0].f.y;   \
             __stcs(o4 + _i, o);   /* speculative t=0 row */                   \
         }                                                                     \
    } while (0)

    // prologue: slots 0..2 are always full (3*256 <= C4)
    ISSUE(0, 0);
    ISSUE(1, 1);
    ISSUE(2, 2);

#pragma unroll 1
    for (int k = 0; k < NIT4; k += NSTG) {
        COMPUTE(0, k);     ISSUE(0, k + 3);
        COMPUTE(1, k + 1); ISSUE(1, k + 4);
        COMPUTE(2, k + 2); ISSUE(2, k + 5);
    }
    CP_WAIT(0);
#undef ISSUE
#undef COMPUTE
#undef STG_SLOT

    // pad one-hot on the speculative row: tid0 of (c==0,m==0) wrote v=0 itself
    if (c == 0 && m == 0 && tid == 0) {
        float* orow = out + (size_t)(b * Mq + m) * Vq;
        float v = __ldcg(orow);
        __stcg(orow, v + sw[0][0]);
    }

    // block-reduce 8 maxes -> g_pmax[b][m][t][c]
    const int lane = tid & 31, wq = tid >> 5;
#pragma unroll
    for (int t = 0; t < Tq; t++) {
        float v = tmax[t];
#pragma unroll
        for (int off = 16; off; off >>= 1)
            v = fmaxf(v, __shfl_xor_sync(0xffffffffu, v, off));
        if (lane == 0) s_red[wq][t] = v;
    }
    __syncthreads();
    if (tid < Tq) {
        float mx = s_red[0][tid];
#pragma unroll
        for (int q = 1; q < 8; q++) mx = fmaxf(mx, s_red[q][tid]);
        g_pmax[((b * Mq + m) * Tq + tid) * CHK + c] = mx;
    }
}

// ---------------------------------------------------------------------------
// K2 (proven): one block per (b,p). Atomics-free scan rebuild, then fixes
// this row only if the t=0 speculation was wrong.
// ---------------------------------------------------------------------------
__global__ __launch_bounds__(TPB) void k_fix(const float* __restrict__ X,
                                             const float* __restrict__ tmplt,
                                             const int*   __restrict__ spans,
                                             float*       __restrict__ out)
{
    const int bx  = blockIdx.x;
    const int b   = bx >> 6;
    const int p   = bx & 63;
    const int tid = threadIdx.x;

    __shared__ int                s_bits[Mq];
    __shared__ unsigned long long s_mask[Tq];
    __shared__ int                s_rowmap[Mq];

    if (tid < Mq) {
        const int mm = tid;
        int mask = 0;
#pragma unroll
        for (int t = 0; t < Tq; t++) {
            const float4 p4 = *reinterpret_cast<const float4*>(
                &g_pmax[((b * Mq + mm) * Tq + t) * CHK]);
            const float mx = fmaxf(fmaxf(p4.x, p4.y), fmaxf(p4.z, p4.w));
            // argmax_v==0 <=> out0(padded) >= raw max (pad weight >= 0; ties -> 0)
            if (g_out0[b * Mq + mm][t] >= mx) mask |= (1 << t);
        }
        s_bits[mm] = mask;
    }
    __syncthreads();

    if (tid < Tq) {
        unsigned long long mk = 0ull;
        for (int mm = 0; mm < Mq; mm++)
            if ((s_bits[mm] >> tid) & 1) mk |= (1ull << mm);
        s_mask[tid] = mk;
    }
    __syncthreads();

    if (tid == 0) {
        int idx = 0;
        for (int t = 0; t < Tq; t++) {
            const unsigned long long mk = s_mask[t];
            const int first = mk ? (__ffsll((long long)mk) - 1) : Mq;
            const int len = min(first, Mq - idx);
            for (int q = idx; q < idx + len; q++)
                s_rowmap[q] = (t << 8) | (q - idx);
            idx += len;
        }
        for (int q = idx; q < Mq; q++) s_rowmap[q] = -1;
    }
    __syncthreads();

    const int rm = s_rowmap[p];
    if (rm == p) return;                    // speculation (t=0, mloc=p) exact

    float* row = out + (size_t)(b * Mq + p) * Vq;

    if (rm < 0) {                           // never written in reference -> zeros
        const float4 z = make_float4(0.f, 0.f, 0.f, 0.f);
        for (int i4 = tid; i4 < V4; i4 += TPB)
            reinterpret_cast<float4*>(row)[i4] = z;
        return;
    }

    const int t = rm >> 8, mloc = rm & 255;
    float wv[NS];
#pragma unroll
    for (int s = 0; s < NS; s++) {
        const float val = tmplt[b * Tq * NS + t * NS + s];
        wv[s] = (s <= spans[b]) ? val : 0.0f;
    }
    const size_t fb = (size_t)b * Nq * MV + (size_t)mloc * Vq;
    for (int i4 = tid; i4 < V4; i4 += TPB) {
        const int v = i4 * 4;
        XU x[Nq]; XU o;
#pragma unroll
        for (int n = 0; n < Nq; n++)
            x[n].f4 = *reinterpret_cast<const float4*>(X + fb + (size_t)n * MV + v);
#pragma unroll
        for (int j = 0; j < 4; j++) {
            float acc = 0.0f;
#pragma unroll
            for (int n = 0; n < Nq; n++) acc = fmaf(wv[n + 1], x[n].f[j], acc);
            o.f[j] = acc;
        }
        if (i4 == 0 && mloc == 0) o.f[0] += wv[0];
        *reinterpret_cast<float4*>(row + v) = o.f4;
    }
}

extern "C" void kernel_launch(void* const* d_in, const int* in_sizes, int n_in,
                              void* d_out, int out_size)
{
    const float* X     = (const float*)d_in[0];
    const float* tmplt = (const float*)d_in[1];
    const int*   spans = (const int*)d_in[2];
    float*       out   = (float*)d_out;

    cudaFuncSetAttribute(k_pass1, cudaFuncAttributeMaxDynamicSharedMemorySize, SMEM_DYN);
    k_pass1<<<Bq * Mq * CHK, TPB, SMEM_DYN>>>(X, tmplt, spans, out);
    k_fix<<<Bq * Mq, TPB>>>(X, tmplt, spans, out);
}

// round 14
// speedup vs baseline: 2.3859x; 1.0027x over previous
#include <cuda_runtime.h>
#include <stdint.h>
#include <float.h>

#define Bq 8
#define Nq 6
#define Mq 64
#define Vq 32000
#define Tq 8
#define NS 7                   // Nq+1 template slots
#define MV (Mq * Vq)
#define MV4 (MV / 4)           // float4 stride between n-planes
#define V4 (Vq / 4)            // 8000 float4 per row
#define CHK 4                  // v-chunks per (b,m) row
#define C4 (V4 / CHK)          // 2000 float4 per chunk
#define NSLOTS 8               // ceil(C4 / TPB)
#define TPB 256
#define NSTG 3                 // bulk-copy pipeline stages
#define SMEM_DYN (NSTG * Nq * TPB * 16)   // 73728 B stage buffer

// scratch (no allocs allowed)
__device__ float g_pmax[Bq * Mq * Tq * CHK];  // [b][m][t][chunk]
__device__ float g_out0[Bq * Mq][Tq];         // out[b,t,m,v=0] (pad included at m==0)

union PU { unsigned long long u; float2 f; };
union XU { float4 f4; float f[4]; };

__device__ __forceinline__ unsigned long long fma2(unsigned long long a,
                                                   unsigned long long b,
                                                   unsigned long long c)
{
    unsigned long long d;
    asm("fma.rn.f32x2 %0, %1, %2, %3;" : "=l"(d) : "l"(a), "l"(b), "l"(c));
    return d;
}

__device__ __forceinline__ void mbar_init(unsigned mbar, unsigned cnt)
{
    asm volatile("mbarrier.init.shared.b64 [%0], %1;" :: "r"(mbar), "r"(cnt) : "memory");
}
__device__ __forceinline__ void mbar_expect_tx(unsigned mbar, unsigned bytes)
{
    asm volatile("mbarrier.arrive.expect_tx.shared.b64 _, [%0], %1;"
                 :: "r"(mbar), "r"(bytes) : "memory");
}
__device__ __forceinline__ void mbar_wait(unsigned mbar, int parity)
{
    asm volatile(
        "{\n\t.reg .pred P;\n\t"
        "W%=:\n\t"
        "mbarrier.try_wait.parity.acquire.cta.shared::cta.b64 P, [%0], %1, 0x989680;\n\t"
        "@!P bra W%=;\n\t}"
        :: "r"(mbar), "r"(parity) : "memory");
}
__device__ __forceinline__ void bulk_cp(unsigned dst_smem, const void* gsrc,
                                        unsigned bytes, unsigned mbar)
{
    asm volatile(
        "cp.async.bulk.shared::cta.global.mbarrier::complete_tx::bytes [%0], [%1], %2, [%3];"
        :: "r"(dst_smem), "l"(gsrc), "r"(bytes), "r"(mbar) : "memory");
}

// ---------------------------------------------------------------------------
// K1: one block per (b,m,chunk). 3-stage cp.async.bulk pipeline: ONE elected
// thread issues 6 bulk copies per slot (zero per-thread load issue); all
// threads wait on mbarrier parity, compute from smem, store with STG.128.
// ---------------------------------------------------------------------------
__global__ __launch_bounds__(TPB, 2)
void k_pass1(const float* __restrict__ X,
             const float* __restrict__ tmplt,
             const int*   __restrict__ spans,
             float*       __restrict__ out)
{
    extern __shared__ float4 stage[];   // [NSTG][Nq][TPB]
    __shared__ unsigned long long smb[NSTG];
    __shared__ float sw[Tq][NS];
    __shared__ float s_red[8][Tq];

    const int task = blockIdx.x;
    const int b = task >> 8;
    const int m = (task >> 2) & 63;
    const int c = task & 3;
    const int tid = threadIdx.x;

    const unsigned stage_base = (unsigned)__cvta_generic_to_shared(stage);
    const unsigned mb0 = (unsigned)__cvta_generic_to_shared(&smb[0]);

    if (tid == 0) {
#pragma unroll
        for (int s = 0; s < NSTG; s++) mbar_init(mb0 + 8 * s, 1);
    }
    if (tid < Tq * NS) {
        const float val = tmplt[b * Tq * NS + tid];
        sw[tid / NS][tid % NS] = ((tid % NS) <= spans[b]) ? val : 0.0f;
    }
    __syncthreads();

    // weights duplicated into packed pairs
    PU w2[Tq][Nq];
#pragma unroll
    for (int t = 0; t < Tq; t++)
#pragma unroll
        for (int n = 0; n < Nq; n++) {
            w2[t][n].f.x = sw[t][n + 1];
            w2[t][n].f.y = sw[t][n + 1];
        }

    const size_t base = (size_t)b * Nq * MV + (size_t)m * Vq;
    const float4* X4  = reinterpret_cast<const float4*>(X) + (base >> 2);
    float4*       o4  = reinterpret_cast<float4*>(out + (size_t)(b * Mq + m) * Vq);

    // pre-step: out0[t] (chunk 0 only)
    if (c == 0 && tid == 0) {
        float xv[Nq];
#pragma unroll
        for (int n = 0; n < Nq; n++) xv[n] = X[base + (size_t)n * MV];
#pragma unroll
        for (int t = 0; t < Tq; t++) {
            float o = 0.0f;
#pragma unroll
            for (int n = 0; n < Nq; n++) o = fmaf(sw[t][n + 1], xv[n], o);
            if (m == 0) o += sw[t][0];
            g_out0[b * Mq + m][t] = o;
        }
    }

    float tmax[Tq];
#pragma unroll
    for (int t = 0; t < Tq; t++) tmax[t] = -FLT_MAX;

    const int i0   = c * C4;
    const int iend = (c + 1) * C4;
    int ph[NSTG] = {0, 0, 0};

    // ISSUE slot k into stage s (tid0 only). Block-uniform guard.
#define ISSUE(s, k)                                                            \
    do { if ((k) < NSLOTS && tid == 0) {                                       \
             const int _st  = i0 + (k) * TPB;                                  \
             const int _cnt = min(TPB, iend - _st);                            \
             mbar_expect_tx(mb0 + 8 * (s), (unsigned)(_cnt * 16 * Nq));        \
             _Pragma("unroll")                                                 \
             for (int n = 0; n < Nq; n++)                                      \
                 bulk_cp(stage_base + ((s) * Nq + n) * TPB * 16,               \
                         X4 + n * MV4 + _st, (unsigned)(_cnt * 16),            \
                         mb0 + 8 * (s));                                       \
         } } while (0)

#define COMPUTE(s, k)                                                          \
    do { if ((k) < NSLOTS) {                                                   \
         mbar_wait(mb0 + 8 * (s), ph[s]); ph[s] ^= 1;                          \
         const int _i = i0 + (k) * TPB + tid;                                  \
         if (_i < iend) {                                                      \
             XU xb[Nq];                                                        \
             _Pragma("unroll")                                                 \
             for (int n = 0; n < Nq; n++)                                      \
                 xb[n].f4 = stage[((s) * Nq + n) * TPB + tid];                 \
             PU acc[Tq];                                                       \
             float2 keep;                                                      \
             _Pragma("unroll")                                                 \
             for (int t = 0; t < Tq; t++) acc[t].u = 0ull;                     \
             _Pragma("unroll")                                                 \
             for (int n = 0; n < Nq; n++) {                                    \
                 PU xp; xp.f.x = xb[n].f[0]; xp.f.y = xb[n].f[1];              \
                 _Pragma("unroll")                                             \
                 for (int t = 0; t < Tq; t++)                                  \
                     acc[t].u = fma2(xp.u, w2[t][n].u, acc[t].u);              \
             }                                                                 \
             _Pragma("unroll")                                                 \
             for (int t = 0; t < Tq; t++)                                      \
                 tmax[t] = fmaxf(tmax[t], fmaxf(acc[t].f.x, acc[t].f.y));      \
             keep = acc[0].f;                                                  \
             _Pragma("unroll")                                                 \
             for (int t = 0; t < Tq; t++) acc[t].u = 0ull;                     \
             _Pragma("unroll")                                                 \
             for (int n = 0; n < Nq; n++) {                                    \
                 PU xp; xp.f.x = xb[n].f[2]; xp.f.y = xb[n].f[3];              \
                 _Pragma("unroll")                                             \
                 for (int t = 0; t < Tq; t++)                                  \
                     acc[t].u = fma2(xp.u, w2[t][n].u, acc[t].u);              \
             }                                                                 \
             _Pragma("unroll")                                                 \
             for (int t = 0; t < Tq; t++)                                      \
                 tmax[t] = fmaxf(tmax[t], fmaxf(acc[t].f.x, acc[t].f.y));      \
             float4 o;                                                         \
             o.x = keep.x; o.y = keep.y; o.z = acc[0].f.x; o.w = acc[0].f.y;   \
             __stcs(o4 + _i, o);                                               \
         }                                                                     \
         __syncthreads();   /* all consumed stage s -> safe to re-issue */     \
         } } while (0)

    // prologue: slots 0..2 (all full: 3*256 <= C4)
    ISSUE(0, 0);
    ISSUE(1, 1);
    ISSUE(2, 2);

#pragma unroll 1
    for (int k = 0; k < NSLOTS; k += NSTG) {
        COMPUTE(0, k);     ISSUE(0, k + 3);
        COMPUTE(1, k + 1); ISSUE(1, k + 4);
        COMPUTE(2, k + 2); ISSUE(2, k + 5);
    }
#undef ISSUE
#undef COMPUTE

    // pad one-hot on the speculative row
    if (c == 0 && m == 0 && tid == 0) {
        float* orow = out + (size_t)(b * Mq + m) * Vq;
        float v = __ldcg(orow);
        __stcg(orow, v + sw[0][0]);
    }

    // block-reduce 8 maxes -> g_pmax[b][m][t][c]
    const int lane = tid & 31, wq = tid >> 5;
#pragma unroll
    for (int t = 0; t < Tq; t++) {
        float v = tmax[t];
#pragma unroll
        for (int off = 16; off; off >>= 1)
            v = fmaxf(v, __shfl_xor_sync(0xffffffffu, v, off));
        if (lane == 0) s_red[wq][t] = v;
    }
    __syncthreads();
    if (tid < Tq) {
        float mx = s_red[0][tid];
#pragma unroll
        for (int q = 1; q < 8; q++) mx = fmaxf(mx, s_red[q][tid]);
        g_pmax[((b * Mq + m) * Tq + tid) * CHK + c] = mx;
    }
}

// ---------------------------------------------------------------------------
// K2: one block per (b,p). Scan rebuilt with an O(8) boundary table;
// fixes this row only if the t=0 speculation was wrong.
// ---------------------------------------------------------------------------
__global__ __launch_bounds__(TPB) void k_fix(const float* __restrict__ X,
                                             const float* __restrict__ tmplt,
                                             const int*   __restrict__ spans,
                                             float*       __restrict__ out)
{
    const int bx  = blockIdx.x;
    const int b   = bx >> 6;
    const int p   = bx & 63;
    const int tid = threadIdx.x;

    __shared__ int                s_bits[Mq];
    __shared__ unsigned long long s_mask[Tq];
    __shared__ int                s_idx[Tq], s_len[Tq];

    if (tid < Mq) {
        const int mm = tid;
        int mask = 0;
#pragma unroll
        for (int t = 0; t < Tq; t++) {
            const float4 p4 = *reinterpret_cast<const float4*>(
                &g_pmax[((b * Mq + mm) * Tq + t) * CHK]);
            const float mx = fmaxf(fmaxf(p4.x, p4.y), fmaxf(p4.z, p4.w));
            // argmax_v==0 <=> out0(padded) >= raw max (pad weight >= 0; ties -> 0)
            if (g_out0[b * Mq + mm][t] >= mx) mask |= (1 << t);
        }
        s_bits[mm] = mask;
    }
    __syncthreads();

    if (tid < Tq) {
        unsigned long long mk = 0ull;
        for (int mm = 0; mm < Mq; mm++)
            if ((s_bits[mm] >> tid) & 1) mk |= (1ull << mm);
        s_mask[tid] = mk;
    }
    __syncthreads();

    if (tid == 0) {
        int idx = 0;
#pragma unroll
        for (int t = 0; t < Tq; t++) {
            const unsigned long long mk = s_mask[t];
            const int first = mk ? (__ffsll((long long)mk) - 1) : Mq;
            const int len = min(first, Mq - idx);
            s_idx[t] = idx; s_len[t] = len;
            idx += len;
        }
    }
    __syncthreads();

    // derive this block's rowmap entry directly from the boundary table
    int rm = -1;
#pragma unroll
    for (int t = 0; t < Tq; t++)
        if (p >= s_idx[t] && p < s_idx[t] + s_len[t]) rm = (t << 8) | (p - s_idx[t]);

    if (rm == p) return;                    // t=0, mloc=p: speculation exact

    float* row = out + (size_t)(b * Mq + p) * Vq;

    if (rm < 0) {                           // never written in reference -> zeros
        const float4 z = make_float4(0.f, 0.f, 0.f, 0.f);
        for (int i4 = tid; i4 < V4; i4 += TPB)
            reinterpret_cast<float4*>(row)[i4] = z;
        return;
    }

    const int t = rm >> 8, mloc = rm & 255;
    float wv[NS];
#pragma unroll
    for (int s = 0; s < NS; s++) {
        const float val = tmplt[b * Tq * NS + t * NS + s];
        wv[s] = (s <= spans[b]) ? val : 0.0f;
    }
    const size_t fb = (size_t)b * Nq * MV + (size_t)mloc * Vq;
    for (int i4 = tid; i4 < V4; i4 += TPB) {
        const int v = i4 * 4;
        XU x[Nq]; XU o;
#pragma unroll
        for (int n = 0; n < Nq; n++)
            x[n].f4 = *reinterpret_cast<const float4*>(X + fb + (size_t)n * MV + v);
#pragma unroll
        for (int j = 0; j < 4; j++) {
            float acc = 0.0f;
#pragma unroll
            for (int n = 0; n < Nq; n++) acc = fmaf(wv[n + 1], x[n].f[j], acc);
            o.f[j] = acc;
        }
        if (i4 == 0 && mloc == 0) o.f[0] += wv[0];
        *reinterpret_cast<float4*>(row + v) = o.f4;
    }
}

extern "C" void kernel_launch(void* const* d_in, const int* in_sizes, int n_in,
                              void* d_out, int out_size)
{
    const float* X     = (const float*)d_in[0];
    const float* tmplt = (const float*)d_in[1];
    const int*   spans = (const int*)d_in[2];
    float*       out   = (float*)d_out;

    cudaFuncSetAttribute(k_pass1, cudaFuncAttributeMaxDynamicSharedMemorySize, SMEM_DYN);
    k_pass1<<<Bq * Mq * CHK, TPB, SMEM_DYN>>>(X, tmplt, spans, out);
    k_fix<<<Bq * Mq, TPB>>>(X, tmplt, spans, out);
}

// round 15
// speedup vs baseline: 2.4273x; 1.0174x over previous
#include <cuda_runtime.h>
#include <stdint.h>
#include <float.h>

#define Bq 8
#define Nq 6
#define Mq 64
#define Vq 32000
#define Tq 8
#define NS 7                   // Nq+1 template slots
#define MV (Mq * Vq)
#define MV4 (MV / 4)           // float4 stride between n-planes
#define V4 (Vq / 4)            // 8000 float4 per row
#define CHK 4                  // v-chunks per (b,m) row
#define C4 (V4 / CHK)          // 2000 float4 per chunk
#define NSLOTS 8               // ceil(C4 / TPB)
#define TPB 256
#define NSTG 3                 // bulk-copy pipeline stages
#define SMEM_DYN (NSTG * Nq * TPB * 16)   // 73728 B stage buffer

// scratch (no allocs allowed)
__device__ float g_pmax[Bq * Mq * Tq * CHK];  // [b][m][t][chunk]
__device__ float g_out0[Bq * Mq][Tq];         // out[b,t,m,v=0] (pad included at m==0)

union PU { unsigned long long u; float2 f; };
union XU { float4 f4; float f[4]; };

__device__ __forceinline__ unsigned long long fma2(unsigned long long a,
                                                   unsigned long long b,
                                                   unsigned long long c)
{
    unsigned long long d;
    asm("fma.rn.f32x2 %0, %1, %2, %3;" : "=l"(d) : "l"(a), "l"(b), "l"(c));
    return d;
}

__device__ __forceinline__ void mbar_init(unsigned mbar, unsigned cnt)
{
    asm volatile("mbarrier.init.shared.b64 [%0], %1;" :: "r"(mbar), "r"(cnt) : "memory");
}
__device__ __forceinline__ void mbar_expect_tx(unsigned mbar, unsigned bytes)
{
    asm volatile("mbarrier.arrive.expect_tx.shared.b64 _, [%0], %1;"
                 :: "r"(mbar), "r"(bytes) : "memory");
}
__device__ __forceinline__ void mbar_wait(unsigned mbar, int parity)
{
    asm volatile(
        "{\n\t.reg .pred P;\n\t"
        "W%=:\n\t"
        "mbarrier.try_wait.parity.acquire.cta.shared::cta.b64 P, [%0], %1, 0x989680;\n\t"
        "@!P bra W%=;\n\t}"
        :: "r"(mbar), "r"(parity) : "memory");
}
__device__ __forceinline__ void bulk_cp(unsigned dst_smem, const void* gsrc,
                                        unsigned bytes, unsigned mbar)
{
    asm volatile(
        "cp.async.bulk.shared::cta.global.mbarrier::complete_tx::bytes [%0], [%1], %2, [%3];"
        :: "r"(dst_smem), "l"(gsrc), "r"(bytes), "r"(mbar) : "memory");
}

// ---------------------------------------------------------------------------
// K1: one block per (b,m,chunk). 3-stage cp.async.bulk pipeline.
// Prologue TMA issues BEFORE the template load (overlap); out0 harvested from
// the slot-0 accumulators (pre-step global loads deleted).
// ---------------------------------------------------------------------------
__global__ __launch_bounds__(TPB, 2)
void k_pass1(const float* __restrict__ X,
             const float* __restrict__ tmplt,
             const int*   __restrict__ spans,
             float*       __restrict__ out)
{
    extern __shared__ float4 stage[];   // [NSTG][Nq][TPB]
    __shared__ unsigned long long smb[NSTG];
    __shared__ float sw[Tq][NS];
    __shared__ float s_red[8][Tq];

    const int task = blockIdx.x;
    const int b = task >> 8;
    const int m = (task >> 2) & 63;
    const int c = task & 3;
    const int tid = threadIdx.x;

    const unsigned stage_base = (unsigned)__cvta_generic_to_shared(stage);
    const unsigned mb0 = (unsigned)__cvta_generic_to_shared(&smb[0]);

    const size_t base = (size_t)b * Nq * MV + (size_t)m * Vq;
    const float4* X4  = reinterpret_cast<const float4*>(X) + (base >> 2);
    float4*       o4  = reinterpret_cast<float4*>(out + (size_t)(b * Mq + m) * Vq);

    const int i0   = c * C4;
    const int iend = (c + 1) * C4;

    // ISSUE slot k into stage s (tid0 only). Block-uniform guard.
#define ISSUE(s, k)                                                            \
    do { if ((k) < NSLOTS && tid == 0) {                                       \
             const int _st  = i0 + (k) * TPB;                                  \
             const int _cnt = min(TPB, iend - _st);                            \
             mbar_expect_tx(mb0 + 8 * (s), (unsigned)(_cnt * 16 * Nq));        \
             _Pragma("unroll")                                                 \
             for (int n = 0; n < Nq; n++)                                      \
                 bulk_cp(stage_base + ((s) * Nq + n) * TPB * 16,               \
                         X4 + n * MV4 + _st, (unsigned)(_cnt * 16),            \
                         mb0 + 8 * (s));                                       \
         } } while (0)

    // ---- pipeline fill FIRST (needs only addresses), template load behind it
    if (tid == 0) {
#pragma unroll
        for (int s = 0; s < NSTG; s++) mbar_init(mb0 + 8 * s, 1);
    }
    ISSUE(0, 0);
    ISSUE(1, 1);
    ISSUE(2, 2);

    if (tid < Tq * NS) {
        const float val = tmplt[b * Tq * NS + tid];
        sw[tid / NS][tid % NS] = ((tid % NS) <= spans[b]) ? val : 0.0f;
    }
    __syncthreads();   // orders mbar_init + sw before any wait/use

    // weights duplicated into packed pairs
    PU w2[Tq][Nq];
#pragma unroll
    for (int t = 0; t < Tq; t++)
#pragma unroll
        for (int n = 0; n < Nq; n++) {
            w2[t][n].f.x = sw[t][n + 1];
            w2[t][n].f.y = sw[t][n + 1];
        }

    float tmax[Tq];
#pragma unroll
    for (int t = 0; t < Tq; t++) tmax[t] = -FLT_MAX;

    int ph[NSTG] = {0, 0, 0};

#define COMPUTE(s, k, FIRST)                                                   \
    do { if ((k) < NSLOTS) {                                                   \
         mbar_wait(mb0 + 8 * (s), ph[s]); ph[s] ^= 1;                          \
         const int _i = i0 + (k) * TPB + tid;                                  \
         if (_i < iend) {                                                      \
             XU xb[Nq];                                                        \
             _Pragma("unroll")                                                 \
             for (int n = 0; n < Nq; n++)                                      \
                 xb[n].f4 = stage[((s) * Nq + n) * TPB + tid];                 \
             PU acc[Tq];                                                       \
             float2 keep;                                                      \
             _Pragma("unroll")                                                 \
             for (int t = 0; t < Tq; t++) acc[t].u = 0ull;                     \
             _Pragma("unroll")                                                 \
             for (int n = 0; n < Nq; n++) {                                    \
                 PU xp; xp.f.x = xb[n].f[0]; xp.f.y = xb[n].f[1];              \
                 _Pragma("unroll")                                             \
                 for (int t = 0; t < Tq; t++)                                  \
                     acc[t].u = fma2(xp.u, w2[t][n].u, acc[t].u);              \
             }                                                                 \
             _Pragma("unroll")                                                 \
             for (int t = 0; t < Tq; t++)                                      \
                 tmax[t] = fmaxf(tmax[t], fmaxf(acc[t].f.x, acc[t].f.y));      \
             if (FIRST && c == 0 && tid == 0) {                                \
                 /* acc[t].f.x == raw weighted value at v=0 */                 \
                 _Pragma("unroll")                                             \
                 for (int t = 0; t < Tq; t++)                                  \
                     g_out0[b * Mq + m][t] =                                   \
                         acc[t].f.x + ((m == 0) ? sw[t][0] : 0.0f);            \
             }                                                                 \
             keep = acc[0].f;                                                  \
             _Pragma("unroll")                                                 \
             for (int t = 0; t < Tq; t++) acc[t].u = 0ull;                     \
             _Pragma("unroll")                                                 \
             for (int n = 0; n < Nq; n++) {                                    \
                 PU xp; xp.f.x = xb[n].f[2]; xp.f.y = xb[n].f[3];              \
                 _Pragma("unroll")                                             \
                 for (int t = 0; t < Tq; t++)                                  \
                     acc[t].u = fma2(xp.u, w2[t][n].u, acc[t].u);              \
             }                                                                 \
             _Pragma("unroll")                                                 \
             for (int t = 0; t < Tq; t++)                                      \
                 tmax[t] = fmaxf(tmax[t], fmaxf(acc[t].f.x, acc[t].f.y));      \
             float4 o;                                                         \
             o.x = keep.x; o.y = keep.y; o.z = acc[0].f.x; o.w = acc[0].f.y;   \
             __stcs(o4 + _i, o);                                               \
         }                                                                     \
         __syncthreads();   /* all consumed stage s -> safe to re-issue */     \
         } } while (0)

#pragma unroll 1
    for (int k = 0; k < NSLOTS; k += NSTG) {
        COMPUTE(0, k, (k == 0)); ISSUE(0, k + 3);
        COMPUTE(1, k + 1, 0);    ISSUE(1, k + 4);
        COMPUTE(2, k + 2, 0);    ISSUE(2, k + 5);
    }
#undef ISSUE
#undef COMPUTE

    // pad one-hot on the speculative row
    if (c == 0 && m == 0 && tid == 0) {
        float* orow = out + (size_t)(b * Mq + m) * Vq;
        float v = __ldcg(orow);
        __stcg(orow, v + sw[0][0]);
    }

    // block-reduce 8 maxes -> g_pmax[b][m][t][c]
    const int lane = tid & 31, wq = tid >> 5;
#pragma unroll
    for (int t = 0; t < Tq; t++) {
        float v = tmax[t];
#pragma unroll
        for (int off = 16; off; off >>= 1)
            v = fmaxf(v, __shfl_xor_sync(0xffffffffu, v, off));
        if (lane == 0) s_red[wq][t] = v;
    }
    __syncthreads();
    if (tid < Tq) {
        float mx = s_red[0][tid];
#pragma unroll
        for (int q = 1; q < 8; q++) mx = fmaxf(mx, s_red[q][tid]);
        g_pmax[((b * Mq + m) * Tq + tid) * CHK + c] = mx;
    }
}

// ---------------------------------------------------------------------------
// K2: one block per (b,p). Ballot-based mask transpose (no 64-iter serial
// loop); O(8) boundary table; fixes this row only if speculation was wrong.
// ---------------------------------------------------------------------------
__global__ __launch_bounds__(TPB) void k_fix(const float* __restrict__ X,
                                             const float* __restrict__ tmplt,
                                             const int*   __restrict__ spans,
                                             float*       __restrict__ out)
{
    const int bx  = blockIdx.x;
    const int b   = bx >> 6;
    const int p   = bx & 63;
    const int tid = threadIdx.x;

    __shared__ unsigned s_lo[Tq], s_hi[Tq];
    __shared__ int      s_idx[Tq], s_len[Tq];

    if (tid < Mq) {
        const int mm = tid;
        int mask = 0;
#pragma unroll
        for (int t = 0; t < Tq; t++) {
            const float4 p4 = *reinterpret_cast<const float4*>(
                &g_pmax[((b * Mq + mm) * Tq + t) * CHK]);
            const float mx = fmaxf(fmaxf(p4.x, p4.y), fmaxf(p4.z, p4.w));
            // argmax_v==0 <=> out0(padded) >= raw max (pad weight >= 0; ties -> 0)
            if (g_out0[b * Mq + mm][t] >= mx) mask |= (1 << t);
        }
        // transpose via ballot: warp0 holds rows 0-31, warp1 rows 32-63
        const int w = tid >> 5;
#pragma unroll
        for (int t = 0; t < Tq; t++) {
            const unsigned bt = __ballot_sync(0xffffffffu, (mask >> t) & 1);
            if ((tid & 31) == t) {
                if (w == 0) s_lo[t] = bt; else s_hi[t] = bt;
            }
        }
    }
    __syncthreads();

    if (tid == 0) {
        int idx = 0;
#pragma unroll
        for (int t = 0; t < Tq; t++) {
            const unsigned long long mk =
                (unsigned long long)s_lo[t] | ((unsigned long long)s_hi[t] << 32);
            const int first = mk ? (__ffsll((long long)mk) - 1) : Mq;
            const int len = min(first, Mq - idx);
            s_idx[t] = idx; s_len[t] = len;
            idx += len;
        }
    }
    __syncthreads();

    // derive this block's rowmap entry from the boundary table
    int rm = -1;
#pragma unroll
    for (int t = 0; t < Tq; t++)
        if (p >= s_idx[t] && p < s_idx[t] + s_len[t]) rm = (t << 8) | (p - s_idx[t]);

    if (rm == p) return;                    // t=0, mloc=p: speculation exact

    float* row = out + (size_t)(b * Mq + p) * Vq;

    if (rm < 0) {                           // never written in reference -> zeros
        const float4 z = make_float4(0.f, 0.f, 0.f, 0.f);
        for (int i4 = tid; i4 < V4; i4 += TPB)
            reinterpret_cast<float4*>(row)[i4] = z;
        return;
    }

    const int t = rm >> 8, mloc = rm & 255;
    float wv[NS];
#pragma unroll
    for (int s = 0; s < NS; s++) {
        const float val = tmplt[b * Tq * NS + t * NS + s];
        wv[s] = (s <= spans[b]) ? val : 0.0f;
    }
    const size_t fb = (size_t)b * Nq * MV + (size_t)mloc * Vq;
    for (int i4 = tid; i4 < V4; i4 += TPB) {
        const int v = i4 * 4;
        XU x[Nq]; XU o;
#pragma unroll
        for (int n = 0; n < Nq; n++)
            x[n].f4 = *reinterpret_cast<const float4*>(X + fb + (size_t)n * MV + v);
#pragma unroll
        for (int j = 0; j < 4; j++) {
            float acc = 0.0f;
#pragma unroll
            for (int n = 0; n < Nq; n++) acc = fmaf(wv[n + 1], x[n].f[j], acc);
            o.f[j] = acc;
        }
        if (i4 == 0 && mloc == 0) o.f[0] += wv[0];
        *reinterpret_cast<float4*>(row + v) = o.f4;
    }
}

extern "C" void kernel_launch(void* const* d_in, const int* in_sizes, int n_in,
                              void* d_out, int out_size)
{
    const float* X     = (const float*)d_in[0];
    const float* tmplt = (const float*)d_in[1];
    const int*   spans = (const int*)d_in[2];
    float*       out   = (float*)d_out;

    cudaFuncSetAttribute(k_pass1, cudaFuncAttributeMaxDynamicSharedMemorySize, SMEM_DYN);
    k_pass1<<<Bq * Mq * CHK, TPB, SMEM_DYN>>>(X, tmplt, spans, out);
    k_fix<<<Bq * Mq, TPB>>>(X, tmplt, spans, out);
}